// round 9
// baseline (speedup 1.0000x reference)
#include <cuda_runtime.h>

#define NNODES 50000
#define CDIM   128
#define HMAX   4
#define EMAXT  450000   // 400000 edges + 50000 self loops

// ---------------- scratch (device globals: allocation-free) ----------------
__device__ __align__(16) float g_h[(long)NNODES * 512];   // post-GEMM features [N, H*C]
__device__ __align__(16) float g_buf1[NNODES * CDIM];     // layer-0 output
__device__ __align__(16) float g_buf2[NNODES * CDIM];     // layer-1 output
__device__ float g_s[NNODES * HMAX];             // per-node src scores
__device__ float g_d[NNODES * HMAX];             // per-node dst scores
__device__ float g_emax[NNODES * HMAX];          // segment max
__device__ float g_denom[NNODES * HMAX];         // segment sum of exp
__device__ float g_ev[(long)EMAXT * HMAX];       // per-edge score / exp value
__device__ float g_stats[2 * CDIM];              // BN: sum, sumsq
__device__ float g_ss[2 * CDIM];                 // BN: scale, shift
__device__ int   g_src[EMAXT];                   // decoded edge sources (int32)
__device__ int   g_dst[EMAXT];                   // decoded edge dests   (int32)
__device__ int   g_is64;                         // edge dtype flag

// ---------------- edge index dtype detection + decode ----------------
// If edge_index is int64 (little-endian, values < 2^31), every odd 32-bit word
// is zero. For int32 data those words are random node ids. Check 128 of them.
__global__ void detect_kernel(const int* __restrict__ raw) {
    __shared__ int nz;
    if (threadIdx.x == 0) nz = 0;
    __syncthreads();
    if (raw[2 * threadIdx.x + 1] != 0) atomicAdd(&nz, 1);
    __syncthreads();
    if (threadIdx.x == 0) g_is64 = (nz == 0) ? 1 : 0;
}

__global__ void decode_kernel(const int* __restrict__ raw, int E, int Etot) {
    int e = blockIdx.x * blockDim.x + threadIdx.x;
    if (e >= Etot) return;
    if (e < E) {
        if (g_is64) {
            g_src[e] = raw[2 * e];
            g_dst[e] = raw[2 * E + 2 * e];
        } else {
            g_src[e] = raw[e];
            g_dst[e] = raw[E + e];
        }
    } else {
        g_src[e] = e - E;
        g_dst[e] = e - E;
    }
}

// ---------------- GEMM: C[n,m] = A[n,k] @ B[k,m] ----------------
// 64x64 tile, BK=16, 256 threads, 4x4 register blocking. K, M multiples of 16/64.
__global__ void gemm_kernel(const float* __restrict__ A, const float* __restrict__ B,
                            float* __restrict__ C, int n, int k, int m) {
    __shared__ float As[16][66];
    __shared__ float Bs[16][64];
    const int tx = threadIdx.x & 15;
    const int ty = threadIdx.x >> 4;
    const int row0 = blockIdx.y * 64;
    const int col0 = blockIdx.x * 64;
    float acc[4][4] = {};

    for (int k0 = 0; k0 < k; k0 += 16) {
#pragma unroll
        for (int s = 0; s < 4; s++) {
            int idx = s * 256 + threadIdx.x;
            int mm = idx >> 4, kk = idx & 15;
            int r = row0 + mm;
            As[kk][mm] = (r < n) ? A[(long)r * k + k0 + kk] : 0.f;
            int kb = idx >> 6, nb = idx & 63;
            Bs[kb][nb] = B[(long)(k0 + kb) * m + col0 + nb];
        }
        __syncthreads();
#pragma unroll
        for (int kk = 0; kk < 16; kk++) {
            float a[4], b[4];
#pragma unroll
            for (int i = 0; i < 4; i++) a[i] = As[kk][ty * 4 + i];
#pragma unroll
            for (int j = 0; j < 4; j++) b[j] = Bs[kk][tx * 4 + j];
#pragma unroll
            for (int i = 0; i < 4; i++)
#pragma unroll
                for (int j = 0; j < 4; j++) acc[i][j] = fmaf(a[i], b[j], acc[i][j]);
        }
        __syncthreads();
    }
#pragma unroll
    for (int i = 0; i < 4; i++) {
        int r = row0 + ty * 4 + i;
        if (r < n) {
#pragma unroll
            for (int j = 0; j < 4; j++)
                C[(long)r * m + col0 + tx * 4 + j] = acc[i][j];
        }
    }
}

// ---------------- per-node attention scores (one warp per (n,h)) ----------------
__global__ void score_kernel(const float* __restrict__ a_src,
                             const float* __restrict__ a_dst, int H) {
    int w = (blockIdx.x * blockDim.x + threadIdx.x) >> 5;
    int lane = threadIdx.x & 31;
    if (w >= NNODES * H) return;
    int n = w / H, h = w - n * H;
    const float4* hp = (const float4*)&g_h[(long)n * H * CDIM + h * CDIM];
    float4 av = ((const float4*)a_src)[h * 32 + lane];
    float4 dv = ((const float4*)a_dst)[h * 32 + lane];
    float4 hv = hp[lane];
    float sa = hv.x * av.x + hv.y * av.y + hv.z * av.z + hv.w * av.w;
    float sd = hv.x * dv.x + hv.y * dv.y + hv.z * dv.z + hv.w * dv.w;
#pragma unroll
    for (int off = 16; off; off >>= 1) {
        sa += __shfl_down_sync(0xffffffffu, sa, off);
        sd += __shfl_down_sync(0xffffffffu, sd, off);
    }
    if (lane == 0) {
        g_s[w] = sa;
        g_d[w] = sd;
        g_emax[w] = -3.0e38f;
        g_denom[w] = 0.f;
    }
}

// ---------------- init y with bias ----------------
__global__ void inity_kernel(float4* __restrict__ y, const float4* __restrict__ b) {
    int i = blockIdx.x * blockDim.x + threadIdx.x;
    if (i < NNODES * (CDIM / 4)) y[i] = b[i & (CDIM / 4 - 1)];
}

__device__ __forceinline__ void atomicMaxFloat(float* addr, float v) {
    if (v >= 0.f) atomicMax((int*)addr, __float_as_int(v));
    else          atomicMin((unsigned int*)addr, __float_as_uint(v));
}

// ---------------- edge pass A: leaky-relu score + segment max ----------------
__global__ void edgeA_kernel(int Etot, int H) {
    int idx = blockIdx.x * blockDim.x + threadIdx.x;
    if (idx >= Etot * H) return;
    int e = idx / H, h = idx - e * H;
    int src = g_src[e], dst = g_dst[e];
    float v = g_s[src * H + h] + g_d[dst * H + h];
    v = v > 0.f ? v : 0.2f * v;
    g_ev[idx] = v;
    atomicMaxFloat(&g_emax[dst * H + h], v);
}

// ---------------- edge pass B: exp + segment sum ----------------
__global__ void edgeB_kernel(int Etot, int H) {
    int idx = blockIdx.x * blockDim.x + threadIdx.x;
    if (idx >= Etot * H) return;
    int e = idx / H, h = idx - e * H;
    int dst = g_dst[e];
    float ex = expf(g_ev[idx] - g_emax[dst * H + h]);
    g_ev[idx] = ex;
    atomicAdd(&g_denom[dst * H + h], ex);
}

// ---------------- edge pass C: alpha-weighted gather/scatter, head mean ----------------
// One warp per edge; float4 gathers of h[src] and red.global.v4 scatter into y[dst].
__global__ void edgeC_kernel(float* __restrict__ y, int Etot, int H, float invH) {
    int t = blockIdx.x * blockDim.x + threadIdx.x;
    int e = t >> 5;
    int lane = t & 31;
    if (e >= Etot) return;
    int src = g_src[e], dst = g_dst[e];
    float4 acc = make_float4(0.f, 0.f, 0.f, 0.f);
    for (int h = 0; h < H; h++) {
        float alpha = g_ev[(long)e * H + h] / (g_denom[dst * H + h] + 1e-16f);
        const float4* hp = (const float4*)&g_h[(long)src * H * CDIM + h * CDIM];
        float4 hv = hp[lane];
        acc.x = fmaf(alpha, hv.x, acc.x);
        acc.y = fmaf(alpha, hv.y, acc.y);
        acc.z = fmaf(alpha, hv.z, acc.z);
        acc.w = fmaf(alpha, hv.w, acc.w);
    }
    float* dstp = &y[dst * CDIM + lane * 4];
    asm volatile("red.global.add.v4.f32 [%0], {%1, %2, %3, %4};"
                 :: "l"(dstp), "f"(acc.x * invH), "f"(acc.y * invH),
                    "f"(acc.z * invH), "f"(acc.w * invH)
                 : "memory");
}

// ---------------- batch norm ----------------
__global__ void statzero_kernel() {
    if (threadIdx.x < 2 * CDIM) g_stats[threadIdx.x] = 0.f;
}

__global__ void stats_kernel(const float* __restrict__ y) {
    int c = threadIdx.x;
    int r0 = blockIdx.x * 64;
    int rend = min(r0 + 64, NNODES);
    float s = 0.f, q = 0.f;
    for (int r = r0; r < rend; r++) {
        float v = y[r * CDIM + c];
        s += v;
        q = fmaf(v, v, q);
    }
    atomicAdd(&g_stats[c], s);
    atomicAdd(&g_stats[CDIM + c], q);
}

__global__ void bnfinal_kernel(const float* __restrict__ gamma,
                               const float* __restrict__ beta) {
    int c = threadIdx.x;
    float mean = g_stats[c] * (1.f / NNODES);
    float var  = g_stats[CDIM + c] * (1.f / NNODES) - mean * mean;
    float rstd = rsqrtf(var + 1e-5f);
    float sc = gamma[c] * rstd;
    g_ss[c] = sc;
    g_ss[CDIM + c] = beta[c] - mean * sc;
}

__global__ void norm_kernel(float* __restrict__ y, int relu) {
    int i = blockIdx.x * blockDim.x + threadIdx.x;
    if (i >= NNODES * CDIM) return;
    int c = i & (CDIM - 1);
    float v = fmaf(y[i], g_ss[c], g_ss[CDIM + c]);
    if (relu) v = fmaxf(v, 0.f);
    y[i] = v;
}

// ---------------- host ----------------
extern "C" void kernel_launch(void* const* d_in, const int* in_sizes, int n_in,
                              void* d_out, int out_size) {
    const float* x = (const float*)d_in[0];
    const int* ei_raw = (const int*)d_in[1];
    int E = in_sizes[1] / 2;   // element count of edge_index is 2*E either dtype
    int Etot = E + NNODES;

    float *hbuf, *buf1, *buf2;
    cudaGetSymbolAddress((void**)&hbuf, g_h);
    cudaGetSymbolAddress((void**)&buf1, g_buf1);
    cudaGetSymbolAddress((void**)&buf2, g_buf2);

    detect_kernel<<<1, 128>>>(ei_raw);
    decode_kernel<<<(Etot + 255) / 256, 256>>>(ei_raw, E, Etot);

    const int Ks[3] = {256, 128, 128};
    const int Hs[3] = {4, 4, 1};
    float* outs[3] = {buf1, buf2, (float*)d_out};

    const float* cur = x;
    for (int L = 0; L < 3; L++) {
        const float* W     = (const float*)d_in[2 + 6 * L];
        const float* asrc  = (const float*)d_in[3 + 6 * L];
        const float* adst  = (const float*)d_in[4 + 6 * L];
        const float* bias  = (const float*)d_in[5 + 6 * L];
        const float* gamma = (const float*)d_in[6 + 6 * L];
        const float* beta  = (const float*)d_in[7 + 6 * L];
        int K = Ks[L], H = Hs[L], M = H * CDIM;
        float* y = outs[L];

        dim3 gg(M / 64, (NNODES + 63) / 64);
        gemm_kernel<<<gg, 256>>>(cur, W, hbuf, NNODES, K, M);

        score_kernel<<<(NNODES * H + 3) / 4, 128>>>(asrc, adst, H);
        inity_kernel<<<(NNODES * (CDIM / 4) + 255) / 256, 256>>>((float4*)y, (const float4*)bias);

        int tot = Etot * H;
        edgeA_kernel<<<(tot + 255) / 256, 256>>>(Etot, H);
        edgeB_kernel<<<(tot + 255) / 256, 256>>>(Etot, H);
        edgeC_kernel<<<(Etot * 32 + 255) / 256, 256>>>(y, Etot, H, 1.f / (float)H);

        statzero_kernel<<<1, 256>>>();
        stats_kernel<<<(NNODES + 63) / 64, CDIM>>>(y);
        bnfinal_kernel<<<1, CDIM>>>(gamma, beta);
        norm_kernel<<<(NNODES * CDIM + 255) / 256, 256>>>(y, (L < 2) ? 1 : 0);

        cur = y;
    }
}

// round 10
// speedup vs baseline: 1.2761x; 1.2761x over previous
#include <cuda_runtime.h>

#define NNODES 50000
#define CDIM   128
#define HMAX   4
#define EMAXT  450000   // 400000 edges + 50000 self loops
#define NSCANB 196      // ceil(50000/256)

// ---------------- scratch (device globals: allocation-free) ----------------
__device__ __align__(16) float g_h[(long)NNODES * 512];   // post-GEMM features [N, H*C]
__device__ __align__(16) float g_buf1[NNODES * CDIM];     // layer-0 output
__device__ __align__(16) float g_buf2[NNODES * CDIM];     // layer-1 output
__device__ float g_s[NNODES * HMAX];             // per-node src scores
__device__ float g_d[NNODES * HMAX];             // per-node dst scores
__device__ float g_stats[2 * CDIM];              // BN: sum, sumsq
__device__ float g_ss[2 * CDIM];                 // BN: scale, shift
__device__ int   g_src[EMAXT];                   // decoded edge sources (int32)
__device__ int   g_dst[EMAXT];                   // decoded edge dests   (int32)
__device__ int   g_is64;                         // edge dtype flag
// CSR by destination
__device__ int   g_cnt[NNODES];
__device__ int   g_fill[NNODES];
__device__ int   g_off[NNODES + 1];
__device__ int   g_bsums[256];
__device__ int   g_bsumx[256];
__device__ int   g_csr_src[EMAXT];

// ---------------- edge index dtype detection + decode ----------------
__global__ void detect_kernel(const int* __restrict__ raw) {
    __shared__ int nz;
    if (threadIdx.x == 0) nz = 0;
    __syncthreads();
    if (raw[2 * threadIdx.x + 1] != 0) atomicAdd(&nz, 1);
    __syncthreads();
    if (threadIdx.x == 0) g_is64 = (nz == 0) ? 1 : 0;
}

__global__ void decode_kernel(const int* __restrict__ raw, int E, int Etot) {
    int e = blockIdx.x * blockDim.x + threadIdx.x;
    if (e >= Etot) return;
    if (e < E) {
        if (g_is64) {
            g_src[e] = raw[2 * e];
            g_dst[e] = raw[2 * E + 2 * e];
        } else {
            g_src[e] = raw[e];
            g_dst[e] = raw[E + e];
        }
    } else {
        g_src[e] = e - E;
        g_dst[e] = e - E;
    }
}

// ---------------- CSR build (by dst) ----------------
__global__ void csr_zero_kernel() {
    int i = blockIdx.x * blockDim.x + threadIdx.x;
    if (i < NNODES) { g_cnt[i] = 0; g_fill[i] = 0; }
}

__global__ void csr_count_kernel(int Etot) {
    int e = blockIdx.x * blockDim.x + threadIdx.x;
    if (e < Etot) atomicAdd(&g_cnt[g_dst[e]], 1);
}

// block-wise inclusive scan; writes partial g_off[i+1], block sums to g_bsums
__global__ void csr_scan1_kernel() {
    __shared__ int sh[256];
    int t = threadIdx.x;
    int i = blockIdx.x * 256 + t;
    int v = (i < NNODES) ? g_cnt[i] : 0;
    sh[t] = v;
    __syncthreads();
#pragma unroll
    for (int d = 1; d < 256; d <<= 1) {
        int add = (t >= d) ? sh[t - d] : 0;
        __syncthreads();
        sh[t] += add;
        __syncthreads();
    }
    if (i < NNODES) g_off[i + 1] = sh[t];
    if (t == 255) g_bsums[blockIdx.x] = sh[255];
}

// exclusive scan of the 196 block sums (single block)
__global__ void csr_scan2_kernel() {
    __shared__ int sh[256];
    int t = threadIdx.x;
    int v = (t < NSCANB) ? g_bsums[t] : 0;
    sh[t] = v;
    __syncthreads();
#pragma unroll
    for (int d = 1; d < 256; d <<= 1) {
        int add = (t >= d) ? sh[t - d] : 0;
        __syncthreads();
        sh[t] += add;
        __syncthreads();
    }
    g_bsumx[t] = sh[t] - v;   // exclusive
}

__global__ void csr_fix_kernel() {
    int i = blockIdx.x * blockDim.x + threadIdx.x;
    if (i < NNODES) g_off[i + 1] += g_bsumx[i >> 8];
    if (i == 0) g_off[0] = 0;
}

__global__ void csr_place_kernel(int Etot) {
    int e = blockIdx.x * blockDim.x + threadIdx.x;
    if (e >= Etot) return;
    int d = g_dst[e];
    int pos = g_off[d] + atomicAdd(&g_fill[d], 1);
    g_csr_src[pos] = g_src[e];
}

// ---------------- GEMM: C[n,m] = A[n,k] @ B[k,m] ----------------
__global__ void gemm_kernel(const float* __restrict__ A, const float* __restrict__ B,
                            float* __restrict__ C, int n, int k, int m) {
    __shared__ float As[16][66];
    __shared__ float Bs[16][64];
    const int tx = threadIdx.x & 15;
    const int ty = threadIdx.x >> 4;
    const int row0 = blockIdx.y * 64;
    const int col0 = blockIdx.x * 64;
    float acc[4][4] = {};

    for (int k0 = 0; k0 < k; k0 += 16) {
#pragma unroll
        for (int s = 0; s < 4; s++) {
            int idx = s * 256 + threadIdx.x;
            int mm = idx >> 4, kk = idx & 15;
            int r = row0 + mm;
            As[kk][mm] = (r < n) ? A[(long)r * k + k0 + kk] : 0.f;
            int kb = idx >> 6, nb = idx & 63;
            Bs[kb][nb] = B[(long)(k0 + kb) * m + col0 + nb];
        }
        __syncthreads();
#pragma unroll
        for (int kk = 0; kk < 16; kk++) {
            float a[4], b[4];
#pragma unroll
            for (int i = 0; i < 4; i++) a[i] = As[kk][ty * 4 + i];
#pragma unroll
            for (int j = 0; j < 4; j++) b[j] = Bs[kk][tx * 4 + j];
#pragma unroll
            for (int i = 0; i < 4; i++)
#pragma unroll
                for (int j = 0; j < 4; j++) acc[i][j] = fmaf(a[i], b[j], acc[i][j]);
        }
        __syncthreads();
    }
#pragma unroll
    for (int i = 0; i < 4; i++) {
        int r = row0 + ty * 4 + i;
        if (r < n) {
#pragma unroll
            for (int j = 0; j < 4; j++)
                C[(long)r * m + col0 + tx * 4 + j] = acc[i][j];
        }
    }
}

// ---------------- per-node attention scores (one warp per (n,h)) ----------------
__global__ void score_kernel(const float* __restrict__ a_src,
                             const float* __restrict__ a_dst, int H) {
    int w = (blockIdx.x * blockDim.x + threadIdx.x) >> 5;
    int lane = threadIdx.x & 31;
    if (w >= NNODES * H) return;
    int n = w / H, h = w - n * H;
    const float4* hp = (const float4*)&g_h[(long)n * H * CDIM + h * CDIM];
    float4 av = ((const float4*)a_src)[h * 32 + lane];
    float4 dv = ((const float4*)a_dst)[h * 32 + lane];
    float4 hv = hp[lane];
    float sa = hv.x * av.x + hv.y * av.y + hv.z * av.z + hv.w * av.w;
    float sd = hv.x * dv.x + hv.y * dv.y + hv.z * dv.z + hv.w * dv.w;
#pragma unroll
    for (int off = 16; off; off >>= 1) {
        sa += __shfl_down_sync(0xffffffffu, sa, off);
        sd += __shfl_down_sync(0xffffffffu, sd, off);
    }
    if (lane == 0) {
        g_s[w] = sa;
        g_d[w] = sd;
    }
}

// ---------------- fused attention: softmax + gather-aggregate + bias ----------------
// One warp per destination node. Two passes over its CSR edge list.
// alpha = exp(e)/sum(exp(e)) (no max subtraction; scores bounded, exp-safe).
template<int H>
__global__ void attn_kernel(const float* __restrict__ hfeat, float* __restrict__ y,
                            const float* __restrict__ bias) {
    int w = (blockIdx.x * blockDim.x + threadIdx.x) >> 5;
    int lane = threadIdx.x & 31;
    if (w >= NNODES) return;
    int rs = g_off[w], re = g_off[w + 1];

    float dv[H];
#pragma unroll
    for (int h = 0; h < H; h++) dv[h] = g_d[w * H + h];

    // pass 1: denominator per head
    float den[H];
#pragma unroll
    for (int h = 0; h < H; h++) den[h] = 0.f;
    for (int i = rs + lane; i < re; i += 32) {
        int src = g_csr_src[i];
#pragma unroll
        for (int h = 0; h < H; h++) {
            float e = g_s[src * H + h] + dv[h];
            e = e > 0.f ? e : 0.2f * e;
            den[h] += expf(e);
        }
    }
#pragma unroll
    for (int h = 0; h < H; h++) {
#pragma unroll
        for (int off = 16; off; off >>= 1)
            den[h] += __shfl_xor_sync(0xffffffffu, den[h], off);
    }
    float inv[H];
#pragma unroll
    for (int h = 0; h < H; h++) inv[h] = 1.f / den[h];

    // pass 2: weighted gather-accumulate (lane owns 4 feature cols per head)
    float4 acc[H];
#pragma unroll
    for (int h = 0; h < H; h++) acc[h] = make_float4(0.f, 0.f, 0.f, 0.f);

    for (int i = rs; i < re; i++) {
        int src = g_csr_src[i];         // same addr for all lanes -> broadcast
        float ex;
        {
            int hh = (H > 1) ? (lane & 3) : 0;
            float e = g_s[src * H + hh] + dv[hh];
            e = e > 0.f ? e : 0.2f * e;
            ex = expf(e);
        }
        const float4* hp = (const float4*)&hfeat[(long)src * (H * CDIM)];
#pragma unroll
        for (int h = 0; h < H; h++) {
            float wgt = ((H > 1) ? __shfl_sync(0xffffffffu, ex, h) : ex) * inv[h];
            float4 v = hp[h * 32 + lane];
            acc[h].x = fmaf(wgt, v.x, acc[h].x);
            acc[h].y = fmaf(wgt, v.y, acc[h].y);
            acc[h].z = fmaf(wgt, v.z, acc[h].z);
            acc[h].w = fmaf(wgt, v.w, acc[h].w);
        }
    }

    float4 o = make_float4(0.f, 0.f, 0.f, 0.f);
#pragma unroll
    for (int h = 0; h < H; h++) {
        o.x += acc[h].x; o.y += acc[h].y; o.z += acc[h].z; o.w += acc[h].w;
    }
    const float invH = 1.f / (float)H;
    float4 b4 = ((const float4*)bias)[lane];
    o.x = fmaf(o.x, invH, b4.x);
    o.y = fmaf(o.y, invH, b4.y);
    o.z = fmaf(o.z, invH, b4.z);
    o.w = fmaf(o.w, invH, b4.w);
    ((float4*)&y[(long)w * CDIM])[lane] = o;
}

// ---------------- batch norm ----------------
__global__ void statzero_kernel() {
    if (threadIdx.x < 2 * CDIM) g_stats[threadIdx.x] = 0.f;
}

__global__ void stats_kernel(const float* __restrict__ y) {
    int c = threadIdx.x;
    int r0 = blockIdx.x * 64;
    int rend = min(r0 + 64, NNODES);
    float s = 0.f, q = 0.f;
    for (int r = r0; r < rend; r++) {
        float v = y[r * CDIM + c];
        s += v;
        q = fmaf(v, v, q);
    }
    atomicAdd(&g_stats[c], s);
    atomicAdd(&g_stats[CDIM + c], q);
}

__global__ void bnfinal_kernel(const float* __restrict__ gamma,
                               const float* __restrict__ beta) {
    int c = threadIdx.x;
    float mean = g_stats[c] * (1.f / NNODES);
    float var  = g_stats[CDIM + c] * (1.f / NNODES) - mean * mean;
    float rstd = rsqrtf(var + 1e-5f);
    float sc = gamma[c] * rstd;
    g_ss[c] = sc;
    g_ss[CDIM + c] = beta[c] - mean * sc;
}

__global__ void norm_kernel(float* __restrict__ y, int relu) {
    int i = blockIdx.x * blockDim.x + threadIdx.x;
    if (i >= NNODES * CDIM) return;
    int c = i & (CDIM - 1);
    float v = fmaf(y[i], g_ss[c], g_ss[CDIM + c]);
    if (relu) v = fmaxf(v, 0.f);
    y[i] = v;
}

// ---------------- host ----------------
extern "C" void kernel_launch(void* const* d_in, const int* in_sizes, int n_in,
                              void* d_out, int out_size) {
    const float* x = (const float*)d_in[0];
    const int* ei_raw = (const int*)d_in[1];
    int E = in_sizes[1] / 2;
    int Etot = E + NNODES;

    float *hbuf, *buf1, *buf2;
    cudaGetSymbolAddress((void**)&hbuf, g_h);
    cudaGetSymbolAddress((void**)&buf1, g_buf1);
    cudaGetSymbolAddress((void**)&buf2, g_buf2);

    detect_kernel<<<1, 128>>>(ei_raw);
    decode_kernel<<<(Etot + 255) / 256, 256>>>(ei_raw, E, Etot);

    // CSR build (by destination)
    csr_zero_kernel<<<(NNODES + 255) / 256, 256>>>();
    csr_count_kernel<<<(Etot + 255) / 256, 256>>>(Etot);
    csr_scan1_kernel<<<NSCANB, 256>>>();
    csr_scan2_kernel<<<1, 256>>>();
    csr_fix_kernel<<<(NNODES + 255) / 256, 256>>>();
    csr_place_kernel<<<(Etot + 255) / 256, 256>>>(Etot);

    const int Ks[3] = {256, 128, 128};
    const int Hs[3] = {4, 4, 1};
    float* outs[3] = {buf1, buf2, (float*)d_out};

    const float* cur = x;
    for (int L = 0; L < 3; L++) {
        const float* W     = (const float*)d_in[2 + 6 * L];
        const float* asrc  = (const float*)d_in[3 + 6 * L];
        const float* adst  = (const float*)d_in[4 + 6 * L];
        const float* bias  = (const float*)d_in[5 + 6 * L];
        const float* gamma = (const float*)d_in[6 + 6 * L];
        const float* beta  = (const float*)d_in[7 + 6 * L];
        int K = Ks[L], H = Hs[L], M = H * CDIM;
        float* y = outs[L];

        dim3 gg(M / 64, (NNODES + 63) / 64);
        gemm_kernel<<<gg, 256>>>(cur, W, hbuf, NNODES, K, M);

        score_kernel<<<(NNODES * H + 3) / 4, 128>>>(asrc, adst, H);

        int ablocks = (NNODES * 32 + 255) / 256;
        if (H == 4) attn_kernel<4><<<ablocks, 256>>>(hbuf, y, bias);
        else        attn_kernel<1><<<ablocks, 256>>>(hbuf, y, bias);

        statzero_kernel<<<1, 256>>>();
        stats_kernel<<<(NNODES + 63) / 64, CDIM>>>(y);
        bnfinal_kernel<<<1, CDIM>>>(gamma, beta);
        norm_kernel<<<(NNODES * CDIM + 255) / 256, 256>>>(y, (L < 2) ? 1 : 0);

        cur = y;
    }
}

// round 13
// speedup vs baseline: 1.6920x; 1.3259x over previous
#include <cuda_runtime.h>
#include <cuda_bf16.h>
#include <cstdint>

#define NNODES 50000
#define CDIM   128
#define HMAX   4
#define EMAXT  450000   // 400000 edges + 50000 self loops
#define NSCANB 196      // ceil(50000/256)

// ---------------- scratch (device globals: allocation-free) ----------------
__device__ __align__(16) float g_h[(long)NNODES * 512];   // post-GEMM features [N, H*C]
__device__ __align__(16) float g_buf1[NNODES * CDIM];     // layer-0 output
__device__ __align__(16) float g_buf2[NNODES * CDIM];     // layer-1 output
__device__ float g_s[NNODES * HMAX];             // per-node src scores
__device__ float g_d[NNODES * HMAX];             // per-node dst scores
__device__ float g_stats[2 * CDIM];              // BN: sum, sumsq
__device__ float g_ss[2 * CDIM];                 // BN: scale, shift
__device__ int   g_src[EMAXT];                   // decoded edge sources (int32)
__device__ int   g_dst[EMAXT];                   // decoded edge dests   (int32)
__device__ int   g_is64;                         // edge dtype flag
// CSR by destination
__device__ int   g_cnt[NNODES];
__device__ int   g_fill[NNODES];
__device__ int   g_off[NNODES + 1];
__device__ int   g_bsums[256];
__device__ int   g_bsumx[256];
__device__ int   g_csr_src[EMAXT];
// bf16 hi/lo split operands for tensor-core GEMM
__device__ __align__(16) __nv_bfloat16 g_abf[(long)NNODES * 512];  // [N, 2K] hi|lo (K<=256)
__device__ __align__(16) __nv_bfloat16 g_bbf[512 * 512];           // [M, 2K] transposed W

// ---------------- edge index dtype detection + decode ----------------
__global__ void detect_kernel(const int* __restrict__ raw) {
    __shared__ int nz;
    if (threadIdx.x == 0) nz = 0;
    __syncthreads();
    if (raw[2 * threadIdx.x + 1] != 0) atomicAdd(&nz, 1);
    __syncthreads();
    if (threadIdx.x == 0) g_is64 = (nz == 0) ? 1 : 0;
}

__global__ void decode_kernel(const int* __restrict__ raw, int E, int Etot) {
    int e = blockIdx.x * blockDim.x + threadIdx.x;
    if (e >= Etot) return;
    if (e < E) {
        if (g_is64) {
            g_src[e] = raw[2 * e];
            g_dst[e] = raw[2 * E + 2 * e];
        } else {
            g_src[e] = raw[e];
            g_dst[e] = raw[E + e];
        }
    } else {
        g_src[e] = e - E;
        g_dst[e] = e - E;
    }
}

// ---------------- CSR build (by dst) ----------------
__global__ void csr_zero_kernel() {
    int i = blockIdx.x * blockDim.x + threadIdx.x;
    if (i < NNODES) { g_cnt[i] = 0; g_fill[i] = 0; }
}

__global__ void csr_count_kernel(int Etot) {
    int e = blockIdx.x * blockDim.x + threadIdx.x;
    if (e < Etot) atomicAdd(&g_cnt[g_dst[e]], 1);
}

__global__ void csr_scan1_kernel() {
    __shared__ int sh[256];
    int t = threadIdx.x;
    int i = blockIdx.x * 256 + t;
    int v = (i < NNODES) ? g_cnt[i] : 0;
    sh[t] = v;
    __syncthreads();
#pragma unroll
    for (int d = 1; d < 256; d <<= 1) {
        int add = (t >= d) ? sh[t - d] : 0;
        __syncthreads();
        sh[t] += add;
        __syncthreads();
    }
    if (i < NNODES) g_off[i + 1] = sh[t];
    if (t == 255) g_bsums[blockIdx.x] = sh[255];
}

__global__ void csr_scan2_kernel() {
    __shared__ int sh[256];
    int t = threadIdx.x;
    int v = (t < NSCANB) ? g_bsums[t] : 0;
    sh[t] = v;
    __syncthreads();
#pragma unroll
    for (int d = 1; d < 256; d <<= 1) {
        int add = (t >= d) ? sh[t - d] : 0;
        __syncthreads();
        sh[t] += add;
        __syncthreads();
    }
    g_bsumx[t] = sh[t] - v;   // exclusive
}

__global__ void csr_fix_kernel() {
    int i = blockIdx.x * blockDim.x + threadIdx.x;
    if (i < NNODES) g_off[i + 1] += g_bsumx[i >> 8];
    if (i == 0) g_off[0] = 0;
}

__global__ void csr_place_kernel(int Etot) {
    int e = blockIdx.x * blockDim.x + threadIdx.x;
    if (e >= Etot) return;
    int d = g_dst[e];
    int pos = g_off[d] + atomicAdd(&g_fill[d], 1);
    g_csr_src[pos] = g_src[e];
}

// ---------------- fp32 -> bf16 hi/lo conversions ----------------
__global__ void convA_kernel(const float* __restrict__ A, __nv_bfloat16* __restrict__ out,
                             long total, int K) {
    long i = (long)blockIdx.x * blockDim.x + threadIdx.x;
    if (i >= total) return;
    int r = (int)(i / K);
    int c = (int)(i - (long)r * K);
    float x = A[i];
    __nv_bfloat16 hi = __float2bfloat16_rn(x);
    float rsd = x - __bfloat162float(hi);
    out[(long)r * 2 * K + c] = hi;
    out[(long)r * 2 * K + K + c] = __float2bfloat16_rn(rsd);
}

// W [K, M] row-major -> out [M, 2K] (transposed, hi|lo)
__global__ void convB_kernel(const float* __restrict__ W, __nv_bfloat16* __restrict__ out,
                             int K, int M) {
    int i = blockIdx.x * blockDim.x + threadIdx.x;
    if (i >= K * M) return;
    int k = i / M, mc = i - k * M;
    float x = W[i];
    __nv_bfloat16 hi = __float2bfloat16_rn(x);
    float rsd = x - __bfloat162float(hi);
    out[(long)mc * 2 * K + k] = hi;
    out[(long)mc * 2 * K + K + k] = __float2bfloat16_rn(rsd);
}

// ---------------- helpers ----------------
__device__ __forceinline__ uint32_t smem_u32(const void* p) {
    uint32_t a;
    asm("{ .reg .u64 t; cvta.to.shared.u64 t, %1; cvt.u32.u64 %0, t; }" : "=r"(a) : "l"(p));
    return a;
}

// ---------------- HMMA GEMM: C[r,m] = A'[r,3K] @ B'[3K,m] (hi/lo split) ----------------
// Block 128x128, BK=32 bf16, 256 threads (8 warps, 4x2), warp tile 32x64.
// A' [rows, 2K] row-major; B' [M, 2K] (n-major -> .col fragment via plain ldmatrix).
#define SPAD 40   // padded smem row stride (bf16 elems): conflict-free ldmatrix
__global__ void __launch_bounds__(256)
mma_gemm_kernel(const __nv_bfloat16* __restrict__ Abf,
                const __nv_bfloat16* __restrict__ Bbf,
                float* __restrict__ C, int nrows, int K, int M) {
    __shared__ __align__(16) __nv_bfloat16 sA[2][128 * SPAD];
    __shared__ __align__(16) __nv_bfloat16 sB[2][128 * SPAD];
    const int tid = threadIdx.x;
    const int lane = tid & 31, wid = tid >> 5;
    const int wm = wid & 3, wn = wid >> 2;    // 4 warps along rows, 2 along cols
    const int row0 = blockIdx.y * 128, col0 = blockIdx.x * 128;
    const int K2 = 2 * K;
    const int cpp = K / 32;                   // chunks per phase
    const int total = 3 * cpp;

    float acc[2][8][4];
#pragma unroll
    for (int mi = 0; mi < 2; mi++)
#pragma unroll
        for (int ni = 0; ni < 8; ni++)
#pragma unroll
            for (int q = 0; q < 4; q++) acc[mi][ni][q] = 0.f;

    auto issue = [&](int gc) {
        int ph = gc / cpp, kc = gc - ph * cpp;
        int aoff = ((ph == 2) ? K : 0) + kc * 32;
        int boff = ((ph == 1) ? K : 0) + kc * 32;
        int st = gc & 1;
#pragma unroll
        for (int u0 = 0; u0 < 2; u0++) {
            int u = u0 * 256 + tid;          // 512 units of 16B per tile
            int r = u >> 2, c8 = (u & 3) << 3;
            uint32_t da = smem_u32(&sA[st][r * SPAD + c8]);
            const void* ga = &Abf[(long)(row0 + r) * K2 + aoff + c8];
            int vsz = (row0 + r < nrows) ? 16 : 0;
            asm volatile("cp.async.cg.shared.global [%0], [%1], 16, %2;"
                         :: "r"(da), "l"(ga), "r"(vsz));
            uint32_t db = smem_u32(&sB[st][r * SPAD + c8]);
            const void* gb = &Bbf[(long)(col0 + r) * K2 + boff + c8];
            asm volatile("cp.async.cg.shared.global [%0], [%1], 16;"
                         :: "r"(db), "l"(gb));
        }
        asm volatile("cp.async.commit_group;");
    };

    issue(0);
#pragma unroll 1
    for (int gc = 0; gc < total; gc++) {
        if (gc + 1 < total) {
            issue(gc + 1);
            asm volatile("cp.async.wait_group 1;");
        } else {
            asm volatile("cp.async.wait_group 0;");
        }
        __syncthreads();
        int st = gc & 1;
#pragma unroll
        for (int ks = 0; ks < 2; ks++) {
            int k0 = ks * 16;
            uint32_t af[2][4];
#pragma unroll
            for (int mi = 0; mi < 2; mi++) {
                int m0i = wm * 32 + mi * 16;
                uint32_t ad = smem_u32(
                    &sA[st][(m0i + (lane & 15)) * SPAD + k0 + ((lane >> 4) << 3)]);
                asm volatile("ldmatrix.sync.aligned.m8n8.x4.shared.b16 {%0,%1,%2,%3}, [%4];"
                             : "=r"(af[mi][0]), "=r"(af[mi][1]),
                               "=r"(af[mi][2]), "=r"(af[mi][3]) : "r"(ad));
            }
            uint32_t bfr[8][2];
#pragma unroll
            for (int p = 0; p < 4; p++) {
                int nb = wn * 64 + p * 16;
                uint32_t ad = smem_u32(
                    &sB[st][(nb + ((lane >> 4) << 3) + (lane & 7)) * SPAD
                            + k0 + (((lane >> 3) & 1) << 3)]);
                uint32_t r0, r1, r2, r3;
                asm volatile("ldmatrix.sync.aligned.m8n8.x4.shared.b16 {%0,%1,%2,%3}, [%4];"
                             : "=r"(r0), "=r"(r1), "=r"(r2), "=r"(r3) : "r"(ad));
                bfr[2 * p][0] = r0;  bfr[2 * p][1] = r1;
                bfr[2 * p + 1][0] = r2;  bfr[2 * p + 1][1] = r3;
            }
#pragma unroll
            for (int mi = 0; mi < 2; mi++)
#pragma unroll
                for (int ni = 0; ni < 8; ni++) {
                    asm volatile(
                        "mma.sync.aligned.m16n8k16.row.col.f32.bf16.bf16.f32 "
                        "{%0,%1,%2,%3}, {%4,%5,%6,%7}, {%8,%9}, {%0,%1,%2,%3};"
                        : "+f"(acc[mi][ni][0]), "+f"(acc[mi][ni][1]),
                          "+f"(acc[mi][ni][2]), "+f"(acc[mi][ni][3])
                        : "r"(af[mi][0]), "r"(af[mi][1]), "r"(af[mi][2]), "r"(af[mi][3]),
                          "r"(bfr[ni][0]), "r"(bfr[ni][1]));
                }
        }
        __syncthreads();
    }

    // epilogue: d0,d1 -> (row, col..col+1); d2,d3 -> (row+8, ...)
#pragma unroll
    for (int mi = 0; mi < 2; mi++)
#pragma unroll
        for (int ni = 0; ni < 8; ni++) {
            int row = row0 + wm * 32 + mi * 16 + (lane >> 2);
            int col = col0 + wn * 64 + ni * 8 + ((lane & 3) << 1);
            if (row < nrows)
                *(float2*)&C[(long)row * M + col] =
                    make_float2(acc[mi][ni][0], acc[mi][ni][1]);
            if (row + 8 < nrows)
                *(float2*)&C[(long)(row + 8) * M + col] =
                    make_float2(acc[mi][ni][2], acc[mi][ni][3]);
        }
}

// ---------------- per-node attention scores (one warp per (n,h)) ----------------
__global__ void score_kernel(const float* __restrict__ a_src,
                             const float* __restrict__ a_dst, int H) {
    int w = (blockIdx.x * blockDim.x + threadIdx.x) >> 5;
    int lane = threadIdx.x & 31;
    if (w >= NNODES * H) return;
    int n = w / H, h = w - n * H;
    const float4* hp = (const float4*)&g_h[(long)n * H * CDIM + h * CDIM];
    float4 av = ((const float4*)a_src)[h * 32 + lane];
    float4 dv = ((const float4*)a_dst)[h * 32 + lane];
    float4 hv = hp[lane];
    float sa = hv.x * av.x + hv.y * av.y + hv.z * av.z + hv.w * av.w;
    float sd = hv.x * dv.x + hv.y * dv.y + hv.z * dv.z + hv.w * dv.w;
#pragma unroll
    for (int off = 16; off; off >>= 1) {
        sa += __shfl_down_sync(0xffffffffu, sa, off);
        sd += __shfl_down_sync(0xffffffffu, sd, off);
    }
    if (lane == 0) {
        g_s[w] = sa;
        g_d[w] = sd;
    }
}

// ---------------- fused attention: softmax + gather-aggregate + bias ----------------
template<int H>
__global__ void attn_kernel(const float* __restrict__ hfeat, float* __restrict__ y,
                            const float* __restrict__ bias) {
    int w = (blockIdx.x * blockDim.x + threadIdx.x) >> 5;
    int lane = threadIdx.x & 31;
    if (w >= NNODES) return;
    int rs = g_off[w], re = g_off[w + 1];

    float dv[H];
#pragma unroll
    for (int h = 0; h < H; h++) dv[h] = g_d[w * H + h];

    float den[H];
#pragma unroll
    for (int h = 0; h < H; h++) den[h] = 0.f;
    for (int i = rs + lane; i < re; i += 32) {
        int src = g_csr_src[i];
#pragma unroll
        for (int h = 0; h < H; h++) {
            float e = g_s[src * H + h] + dv[h];
            e = e > 0.f ? e : 0.2f * e;
            den[h] += expf(e);
        }
    }
#pragma unroll
    for (int h = 0; h < H; h++) {
#pragma unroll
        for (int off = 16; off; off >>= 1)
            den[h] += __shfl_xor_sync(0xffffffffu, den[h], off);
    }
    float inv[H];
#pragma unroll
    for (int h = 0; h < H; h++) inv[h] = 1.f / den[h];

    float4 acc[H];
#pragma unroll
    for (int h = 0; h < H; h++) acc[h] = make_float4(0.f, 0.f, 0.f, 0.f);

    for (int i = rs; i < re; i++) {
        int src = g_csr_src[i];
        float ex;
        {
            int hh = (H > 1) ? (lane & 3) : 0;
            float e = g_s[src * H + hh] + dv[hh];
            e = e > 0.f ? e : 0.2f * e;
            ex = expf(e);
        }
        const float4* hp = (const float4*)&hfeat[(long)src * (H * CDIM)];
#pragma unroll
        for (int h = 0; h < H; h++) {
            float wgt = ((H > 1) ? __shfl_sync(0xffffffffu, ex, h) : ex) * inv[h];
            float4 v = hp[h * 32 + lane];
            acc[h].x = fmaf(wgt, v.x, acc[h].x);
            acc[h].y = fmaf(wgt, v.y, acc[h].y);
            acc[h].z = fmaf(wgt, v.z, acc[h].z);
            acc[h].w = fmaf(wgt, v.w, acc[h].w);
        }
    }

    float4 o = make_float4(0.f, 0.f, 0.f, 0.f);
#pragma unroll
    for (int h = 0; h < H; h++) {
        o.x += acc[h].x; o.y += acc[h].y; o.z += acc[h].z; o.w += acc[h].w;
    }
    const float invH = 1.f / (float)H;
    float4 b4 = ((const float4*)bias)[lane];
    o.x = fmaf(o.x, invH, b4.x);
    o.y = fmaf(o.y, invH, b4.y);
    o.z = fmaf(o.z, invH, b4.z);
    o.w = fmaf(o.w, invH, b4.w);
    ((float4*)&y[(long)w * CDIM])[lane] = o;
}

// ---------------- batch norm ----------------
__global__ void statzero_kernel() {
    if (threadIdx.x < 2 * CDIM) g_stats[threadIdx.x] = 0.f;
}

__global__ void stats_kernel(const float* __restrict__ y) {
    int c = threadIdx.x;
    int r0 = blockIdx.x * 64;
    int rend = min(r0 + 64, NNODES);
    float s = 0.f, q = 0.f;
    for (int r = r0; r < rend; r++) {
        float v = y[r * CDIM + c];
        s += v;
        q = fmaf(v, v, q);
    }
    atomicAdd(&g_stats[c], s);
    atomicAdd(&g_stats[CDIM + c], q);
}

__global__ void bnfinal_kernel(const float* __restrict__ gamma,
                               const float* __restrict__ beta) {
    int c = threadIdx.x;
    float mean = g_stats[c] * (1.f / NNODES);
    float var  = g_stats[CDIM + c] * (1.f / NNODES) - mean * mean;
    float rstd = rsqrtf(var + 1e-5f);
    float sc = gamma[c] * rstd;
    g_ss[c] = sc;
    g_ss[CDIM + c] = beta[c] - mean * sc;
}

__global__ void norm_kernel(float* __restrict__ y, int relu) {
    int i = blockIdx.x * blockDim.x + threadIdx.x;
    if (i >= NNODES * CDIM) return;
    int c = i & (CDIM - 1);
    float v = fmaf(y[i], g_ss[c], g_ss[CDIM + c]);
    if (relu) v = fmaxf(v, 0.f);
    y[i] = v;
}

// ---------------- host ----------------
extern "C" void kernel_launch(void* const* d_in, const int* in_sizes, int n_in,
                              void* d_out, int out_size) {
    const float* x = (const float*)d_in[0];
    const int* ei_raw = (const int*)d_in[1];
    int E = in_sizes[1] / 2;
    int Etot = E + NNODES;

    float *hbuf, *buf1, *buf2;
    cudaGetSymbolAddress((void**)&hbuf, g_h);
    cudaGetSymbolAddress((void**)&buf1, g_buf1);
    cudaGetSymbolAddress((void**)&buf2, g_buf2);
    __nv_bfloat16 *abf, *bbf;
    cudaGetSymbolAddress((void**)&abf, g_abf);
    cudaGetSymbolAddress((void**)&bbf, g_bbf);

    detect_kernel<<<1, 128>>>(ei_raw);
    decode_kernel<<<(Etot + 255) / 256, 256>>>(ei_raw, E, Etot);

    csr_zero_kernel<<<(NNODES + 255) / 256, 256>>>();
    csr_count_kernel<<<(Etot + 255) / 256, 256>>>(Etot);
    csr_scan1_kernel<<<NSCANB, 256>>>();
    csr_scan2_kernel<<<1, 256>>>();
    csr_fix_kernel<<<(NNODES + 255) / 256, 256>>>();
    csr_place_kernel<<<(Etot + 255) / 256, 256>>>(Etot);

    const int Ks[3] = {256, 128, 128};
    const int Hs[3] = {4, 4, 1};
    float* outs[3] = {buf1, buf2, (float*)d_out};

    const float* cur = x;
    for (int L = 0; L < 3; L++) {
        const float* W     = (const float*)d_in[2 + 6 * L];
        const float* asrc  = (const float*)d_in[3 + 6 * L];
        const float* adst  = (const float*)d_in[4 + 6 * L];
        const float* bias  = (const float*)d_in[5 + 6 * L];
        const float* gamma = (const float*)d_in[6 + 6 * L];
        const float* beta  = (const float*)d_in[7 + 6 * L];
        int K = Ks[L], H = Hs[L], M = H * CDIM;
        float* y = outs[L];

        long atot = (long)NNODES * K;
        convA_kernel<<<(int)((atot + 255) / 256), 256>>>(cur, abf, atot, K);
        convB_kernel<<<(K * M + 255) / 256, 256>>>(W, bbf, K, M);

        dim3 gg(M / 128, (NNODES + 127) / 128);
        mma_gemm_kernel<<<gg, 256>>>(abf, bbf, hbuf, NNODES, K, M);

        score_kernel<<<(NNODES * H + 3) / 4, 128>>>(asrc, adst, H);

        int ablocks = (NNODES * 32 + 255) / 256;
        if (H == 4) attn_kernel<4><<<ablocks, 256>>>(hbuf, y, bias);
        else        attn_kernel<1><<<ablocks, 256>>>(hbuf, y, bias);

        statzero_kernel<<<1, 256>>>();
        stats_kernel<<<(NNODES + 63) / 64, CDIM>>>(y);
        bnfinal_kernel<<<1, CDIM>>>(gamma, beta);
        norm_kernel<<<(NNODES * CDIM + 255) / 256, 256>>>(y, (L < 2) ? 1 : 0);

        cur = y;
    }
}

// round 14
// speedup vs baseline: 1.8843x; 1.1137x over previous
#include <cuda_runtime.h>
#include <cuda_bf16.h>
#include <cstdint>

#define NNODES 50000
#define CDIM   128
#define HMAX   4
#define EMAXT  450000   // 400000 edges + 50000 self loops
#define NSCANB 196      // ceil(50000/256)

// ---------------- scratch (device globals: allocation-free) ----------------
__device__ __align__(16) float g_h[(long)NNODES * 512];   // post-GEMM features [N, H*C]
__device__ __align__(16) float g_buf1[NNODES * CDIM];     // layer-0 output
__device__ __align__(16) float g_buf2[NNODES * CDIM];     // layer-1 output
__device__ float g_s[NNODES * HMAX];             // per-node src scores
__device__ float g_d[NNODES * HMAX];             // per-node dst scores
__device__ float g_stats[2 * CDIM];              // BN: sum, sumsq
__device__ float g_ss[2 * CDIM];                 // BN: scale, shift
__device__ int   g_src[EMAXT];                   // decoded edge sources (int32)
__device__ int   g_dst[EMAXT];                   // decoded edge dests   (int32)
__device__ int   g_is64;                         // edge dtype flag
// CSR by destination
__device__ int   g_cnt[NNODES];
__device__ int   g_fill[NNODES];
__device__ int   g_off[NNODES + 1];
__device__ int   g_bsums[256];
__device__ int   g_bsumx[256];
__device__ int   g_csr_src[EMAXT];
// bf16 hi/lo split operands for tensor-core GEMM
__device__ __align__(16) __nv_bfloat16 g_abf[(long)NNODES * 512];  // [N, 2K] hi|lo (K<=256)
__device__ __align__(16) __nv_bfloat16 g_bbf[512 * 512];           // [M, 2K] transposed W

// ---------------- edge index dtype detection + decode ----------------
__global__ void detect_kernel(const int* __restrict__ raw) {
    __shared__ int nz;
    if (threadIdx.x == 0) nz = 0;
    __syncthreads();
    if (raw[2 * threadIdx.x + 1] != 0) atomicAdd(&nz, 1);
    __syncthreads();
    if (threadIdx.x == 0) g_is64 = (nz == 0) ? 1 : 0;
}

__global__ void decode_kernel(const int* __restrict__ raw, int E, int Etot) {
    int e = blockIdx.x * blockDim.x + threadIdx.x;
    if (e >= Etot) return;
    if (e < E) {
        if (g_is64) {
            g_src[e] = raw[2 * e];
            g_dst[e] = raw[2 * E + 2 * e];
        } else {
            g_src[e] = raw[e];
            g_dst[e] = raw[E + e];
        }
    } else {
        g_src[e] = e - E;
        g_dst[e] = e - E;
    }
}

// ---------------- CSR build (by dst) ----------------
__global__ void csr_zero_kernel() {
    int i = blockIdx.x * blockDim.x + threadIdx.x;
    if (i < NNODES) { g_cnt[i] = 0; g_fill[i] = 0; }
    if (blockIdx.x == 0 && threadIdx.x < 2 * CDIM) g_stats[threadIdx.x] = 0.f;
}

__global__ void csr_count_kernel(int Etot) {
    int e = blockIdx.x * blockDim.x + threadIdx.x;
    if (e < Etot) atomicAdd(&g_cnt[g_dst[e]], 1);
}

__global__ void csr_scan1_kernel() {
    __shared__ int sh[256];
    int t = threadIdx.x;
    int i = blockIdx.x * 256 + t;
    int v = (i < NNODES) ? g_cnt[i] : 0;
    sh[t] = v;
    __syncthreads();
#pragma unroll
    for (int d = 1; d < 256; d <<= 1) {
        int add = (t >= d) ? sh[t - d] : 0;
        __syncthreads();
        sh[t] += add;
        __syncthreads();
    }
    if (i < NNODES) g_off[i + 1] = sh[t];
    if (t == 255) g_bsums[blockIdx.x] = sh[255];
}

__global__ void csr_scan2_kernel() {
    __shared__ int sh[256];
    int t = threadIdx.x;
    int v = (t < NSCANB) ? g_bsums[t] : 0;
    sh[t] = v;
    __syncthreads();
#pragma unroll
    for (int d = 1; d < 256; d <<= 1) {
        int add = (t >= d) ? sh[t - d] : 0;
        __syncthreads();
        sh[t] += add;
        __syncthreads();
    }
    g_bsumx[t] = sh[t] - v;   // exclusive
}

__global__ void csr_fix_kernel() {
    int i = blockIdx.x * blockDim.x + threadIdx.x;
    if (i < NNODES) g_off[i + 1] += g_bsumx[i >> 8];
    if (i == 0) g_off[0] = 0;
}

__global__ void csr_place_kernel(int Etot) {
    int e = blockIdx.x * blockDim.x + threadIdx.x;
    if (e >= Etot) return;
    int d = g_dst[e];
    int pos = g_off[d] + atomicAdd(&g_fill[d], 1);
    g_csr_src[pos] = g_src[e];
}

// ---------------- fp32 -> bf16 hi/lo conversion (layer-0 input only) ----------------
// Also zeroes g_s/g_d score accumulators for the upcoming GEMM epilogue.
__global__ void convA_kernel(const float* __restrict__ A, __nv_bfloat16* __restrict__ out,
                             long total, int K) {
    long i = (long)blockIdx.x * blockDim.x + threadIdx.x;
    if (i >= total) return;
    if (i < NNODES * HMAX) { g_s[i] = 0.f; g_d[i] = 0.f; }
    int r = (int)(i / K);
    int c = (int)(i - (long)r * K);
    float x = A[i];
    __nv_bfloat16 hi = __float2bfloat16_rn(x);
    float rsd = x - __bfloat162float(hi);
    out[(long)r * 2 * K + c] = hi;
    out[(long)r * 2 * K + K + c] = __float2bfloat16_rn(rsd);
}

// W [K, M] row-major -> out [M, 2K] (transposed, hi|lo)
__global__ void convB_kernel(const float* __restrict__ W, __nv_bfloat16* __restrict__ out,
                             int K, int M) {
    int i = blockIdx.x * blockDim.x + threadIdx.x;
    if (i >= K * M) return;
    int k = i / M, mc = i - k * M;
    float x = W[i];
    __nv_bfloat16 hi = __float2bfloat16_rn(x);
    float rsd = x - __bfloat162float(hi);
    out[(long)mc * 2 * K + k] = hi;
    out[(long)mc * 2 * K + K + k] = __float2bfloat16_rn(rsd);
}

// ---------------- helpers ----------------
__device__ __forceinline__ uint32_t smem_u32(const void* p) {
    uint32_t a;
    asm("{ .reg .u64 t; cvta.to.shared.u64 t, %1; cvt.u32.u64 %0, t; }" : "=r"(a) : "l"(p));
    return a;
}

// ---------------- HMMA GEMM: C[r,m] = A'[r,3K] @ B'[3K,m] (hi/lo split) ----------------
// Block 128x128, BK=32 bf16, 256 threads (8 warps, 4x2), warp tile 32x64.
// A' [rows, 2K] row-major; B' [M, 2K] (n-major -> .col fragment via plain ldmatrix).
// Epilogue also computes attention scores s = C·a_src, d = C·a_dst per (row, head):
// the 128-col block tile equals exactly one head, so head = blockIdx.x.
#define SPAD 40   // padded smem row stride (bf16 elems): conflict-free ldmatrix
__global__ void __launch_bounds__(256)
mma_gemm_kernel(const __nv_bfloat16* __restrict__ Abf,
                const __nv_bfloat16* __restrict__ Bbf,
                float* __restrict__ C, int nrows, int K, int M,
                const float* __restrict__ a_src, const float* __restrict__ a_dst,
                int H) {
    __shared__ __align__(16) __nv_bfloat16 sA[2][128 * SPAD];
    __shared__ __align__(16) __nv_bfloat16 sB[2][128 * SPAD];
    const int tid = threadIdx.x;
    const int lane = tid & 31, wid = tid >> 5;
    const int wm = wid & 3, wn = wid >> 2;    // 4 warps along rows, 2 along cols
    const int row0 = blockIdx.y * 128, col0 = blockIdx.x * 128;
    const int K2 = 2 * K;
    const int cpp = K / 32;                   // chunks per phase
    const int total = 3 * cpp;

    float acc[2][8][4];
#pragma unroll
    for (int mi = 0; mi < 2; mi++)
#pragma unroll
        for (int ni = 0; ni < 8; ni++)
#pragma unroll
            for (int q = 0; q < 4; q++) acc[mi][ni][q] = 0.f;

    auto issue = [&](int gc) {
        int ph = gc / cpp, kc = gc - ph * cpp;
        int aoff = ((ph == 2) ? K : 0) + kc * 32;
        int boff = ((ph == 1) ? K : 0) + kc * 32;
        int st = gc & 1;
#pragma unroll
        for (int u0 = 0; u0 < 2; u0++) {
            int u = u0 * 256 + tid;          // 512 units of 16B per tile
            int r = u >> 2, c8 = (u & 3) << 3;
            uint32_t da = smem_u32(&sA[st][r * SPAD + c8]);
            const void* ga = &Abf[(long)(row0 + r) * K2 + aoff + c8];
            int vsz = (row0 + r < nrows) ? 16 : 0;
            asm volatile("cp.async.cg.shared.global [%0], [%1], 16, %2;"
                         :: "r"(da), "l"(ga), "r"(vsz));
            uint32_t db = smem_u32(&sB[st][r * SPAD + c8]);
            const void* gb = &Bbf[(long)(col0 + r) * K2 + boff + c8];
            asm volatile("cp.async.cg.shared.global [%0], [%1], 16;"
                         :: "r"(db), "l"(gb));
        }
        asm volatile("cp.async.commit_group;");
    };

    issue(0);
#pragma unroll 1
    for (int gc = 0; gc < total; gc++) {
        if (gc + 1 < total) {
            issue(gc + 1);
            asm volatile("cp.async.wait_group 1;");
        } else {
            asm volatile("cp.async.wait_group 0;");
        }
        __syncthreads();
        int st = gc & 1;
#pragma unroll
        for (int ks = 0; ks < 2; ks++) {
            int k0 = ks * 16;
            uint32_t af[2][4];
#pragma unroll
            for (int mi = 0; mi < 2; mi++) {
                int m0i = wm * 32 + mi * 16;
                uint32_t ad = smem_u32(
                    &sA[st][(m0i + (lane & 15)) * SPAD + k0 + ((lane >> 4) << 3)]);
                asm volatile("ldmatrix.sync.aligned.m8n8.x4.shared.b16 {%0,%1,%2,%3}, [%4];"
                             : "=r"(af[mi][0]), "=r"(af[mi][1]),
                               "=r"(af[mi][2]), "=r"(af[mi][3]) : "r"(ad));
            }
            uint32_t bfr[8][2];
#pragma unroll
            for (int p = 0; p < 4; p++) {
                int nb = wn * 64 + p * 16;
                uint32_t ad = smem_u32(
                    &sB[st][(nb + ((lane >> 4) << 3) + (lane & 7)) * SPAD
                            + k0 + (((lane >> 3) & 1) << 3)]);
                uint32_t r0, r1, r2, r3;
                asm volatile("ldmatrix.sync.aligned.m8n8.x4.shared.b16 {%0,%1,%2,%3}, [%4];"
                             : "=r"(r0), "=r"(r1), "=r"(r2), "=r"(r3) : "r"(ad));
                bfr[2 * p][0] = r0;  bfr[2 * p][1] = r1;
                bfr[2 * p + 1][0] = r2;  bfr[2 * p + 1][1] = r3;
            }
#pragma unroll
            for (int mi = 0; mi < 2; mi++)
#pragma unroll
                for (int ni = 0; ni < 8; ni++) {
                    asm volatile(
                        "mma.sync.aligned.m16n8k16.row.col.f32.bf16.bf16.f32 "
                        "{%0,%1,%2,%3}, {%4,%5,%6,%7}, {%8,%9}, {%0,%1,%2,%3};"
                        : "+f"(acc[mi][ni][0]), "+f"(acc[mi][ni][1]),
                          "+f"(acc[mi][ni][2]), "+f"(acc[mi][ni][3])
                        : "r"(af[mi][0]), "r"(af[mi][1]), "r"(af[mi][2]), "r"(af[mi][3]),
                          "r"(bfr[ni][0]), "r"(bfr[ni][1]));
                }
        }
        __syncthreads();
    }

    // epilogue 1: write C. d0,d1 -> (row, col..col+1); d2,d3 -> (row+8, ...)
#pragma unroll
    for (int mi = 0; mi < 2; mi++)
#pragma unroll
        for (int ni = 0; ni < 8; ni++) {
            int row = row0 + wm * 32 + mi * 16 + (lane >> 2);
            int col = col0 + wn * 64 + ni * 8 + ((lane & 3) << 1);
            if (row < nrows)
                *(float2*)&C[(long)row * M + col] =
                    make_float2(acc[mi][ni][0], acc[mi][ni][1]);
            if (row + 8 < nrows)
                *(float2*)&C[(long)(row + 8) * M + col] =
                    make_float2(acc[mi][ni][2], acc[mi][ni][3]);
        }

    // epilogue 2: fused attention scores. head = blockIdx.x (128-col tile == head).
    {
        int h = blockIdx.x;
        float av[16], dvv[16];
#pragma unroll
        for (int ni = 0; ni < 8; ni++) {
#pragma unroll
            for (int q = 0; q < 2; q++) {
                int cc = wn * 64 + ni * 8 + ((lane & 3) << 1) + q;
                av[ni * 2 + q]  = a_src[h * CDIM + cc];
                dvv[ni * 2 + q] = a_dst[h * CDIM + cc];
            }
        }
        float sp[2][2] = {}, dp[2][2] = {};
#pragma unroll
        for (int mi = 0; mi < 2; mi++)
#pragma unroll
            for (int ni = 0; ni < 8; ni++) {
                sp[mi][0] = fmaf(av[2 * ni], acc[mi][ni][0],
                             fmaf(av[2 * ni + 1], acc[mi][ni][1], sp[mi][0]));
                sp[mi][1] = fmaf(av[2 * ni], acc[mi][ni][2],
                             fmaf(av[2 * ni + 1], acc[mi][ni][3], sp[mi][1]));
                dp[mi][0] = fmaf(dvv[2 * ni], acc[mi][ni][0],
                             fmaf(dvv[2 * ni + 1], acc[mi][ni][1], dp[mi][0]));
                dp[mi][1] = fmaf(dvv[2 * ni], acc[mi][ni][2],
                             fmaf(dvv[2 * ni + 1], acc[mi][ni][3], dp[mi][1]));
            }
#pragma unroll
        for (int mi = 0; mi < 2; mi++)
#pragma unroll
            for (int hf = 0; hf < 2; hf++) {
                float s = sp[mi][hf], d = dp[mi][hf];
                s += __shfl_xor_sync(0xffffffffu, s, 1);
                s += __shfl_xor_sync(0xffffffffu, s, 2);
                d += __shfl_xor_sync(0xffffffffu, d, 1);
                d += __shfl_xor_sync(0xffffffffu, d, 2);
                if ((lane & 3) == 0) {
                    int row = row0 + wm * 32 + mi * 16 + (lane >> 2) + hf * 8;
                    if (row < nrows) {
                        atomicAdd(&g_s[row * H + h], s);
                        atomicAdd(&g_d[row * H + h], d);
                    }
                }
            }
    }
}

// ---------------- fused attention: softmax + gather-aggregate + bias ----------------
template<int H>
__global__ void attn_kernel(const float* __restrict__ hfeat, float* __restrict__ y,
                            const float* __restrict__ bias) {
    int w = (blockIdx.x * blockDim.x + threadIdx.x) >> 5;
    int lane = threadIdx.x & 31;
    if (w >= NNODES) return;
    int rs = g_off[w], re = g_off[w + 1];

    float dv[H];
#pragma unroll
    for (int h = 0; h < H; h++) dv[h] = g_d[w * H + h];

    float den[H];
#pragma unroll
    for (int h = 0; h < H; h++) den[h] = 0.f;
    for (int i = rs + lane; i < re; i += 32) {
        int src = g_csr_src[i];
#pragma unroll
        for (int h = 0; h < H; h++) {
            float e = g_s[src * H + h] + dv[h];
            e = e > 0.f ? e : 0.2f * e;
            den[h] += expf(e);
        }
    }
#pragma unroll
    for (int h = 0; h < H; h++) {
#pragma unroll
        for (int off = 16; off; off >>= 1)
            den[h] += __shfl_xor_sync(0xffffffffu, den[h], off);
    }
    float inv[H];
#pragma unroll
    for (int h = 0; h < H; h++) inv[h] = 1.f / den[h];

    float4 acc[H];
#pragma unroll
    for (int h = 0; h < H; h++) acc[h] = make_float4(0.f, 0.f, 0.f, 0.f);

    const int hh = (H > 1) ? (lane & 3) : 0;
    int i = rs;
    for (; i + 1 < re; i += 2) {
        int s0 = g_csr_src[i], s1 = g_csr_src[i + 1];
        float e0 = g_s[s0 * H + hh] + dv[hh];
        e0 = e0 > 0.f ? e0 : 0.2f * e0;
        float x0 = expf(e0);
        float e1 = g_s[s1 * H + hh] + dv[hh];
        e1 = e1 > 0.f ? e1 : 0.2f * e1;
        float x1 = expf(e1);
        const float4* p0 = (const float4*)&hfeat[(long)s0 * (H * CDIM)];
        const float4* p1 = (const float4*)&hfeat[(long)s1 * (H * CDIM)];
#pragma unroll
        for (int h = 0; h < H; h++) {
            float w0 = ((H > 1) ? __shfl_sync(0xffffffffu, x0, h) : x0) * inv[h];
            float w1 = ((H > 1) ? __shfl_sync(0xffffffffu, x1, h) : x1) * inv[h];
            float4 v0 = p0[h * 32 + lane];
            float4 v1 = p1[h * 32 + lane];
            acc[h].x = fmaf(w0, v0.x, fmaf(w1, v1.x, acc[h].x));
            acc[h].y = fmaf(w0, v0.y, fmaf(w1, v1.y, acc[h].y));
            acc[h].z = fmaf(w0, v0.z, fmaf(w1, v1.z, acc[h].z));
            acc[h].w = fmaf(w0, v0.w, fmaf(w1, v1.w, acc[h].w));
        }
    }
    if (i < re) {
        int s0 = g_csr_src[i];
        float e0 = g_s[s0 * H + hh] + dv[hh];
        e0 = e0 > 0.f ? e0 : 0.2f * e0;
        float x0 = expf(e0);
        const float4* p0 = (const float4*)&hfeat[(long)s0 * (H * CDIM)];
#pragma unroll
        for (int h = 0; h < H; h++) {
            float w0 = ((H > 1) ? __shfl_sync(0xffffffffu, x0, h) : x0) * inv[h];
            float4 v0 = p0[h * 32 + lane];
            acc[h].x = fmaf(w0, v0.x, acc[h].x);
            acc[h].y = fmaf(w0, v0.y, acc[h].y);
            acc[h].z = fmaf(w0, v0.z, acc[h].z);
            acc[h].w = fmaf(w0, v0.w, acc[h].w);
        }
    }

    float4 o = make_float4(0.f, 0.f, 0.f, 0.f);
#pragma unroll
    for (int h = 0; h < H; h++) {
        o.x += acc[h].x; o.y += acc[h].y; o.z += acc[h].z; o.w += acc[h].w;
    }
    const float invH = 1.f / (float)H;
    float4 b4 = ((const float4*)bias)[lane];
    o.x = fmaf(o.x, invH, b4.x);
    o.y = fmaf(o.y, invH, b4.y);
    o.z = fmaf(o.z, invH, b4.z);
    o.w = fmaf(o.w, invH, b4.w);
    ((float4*)&y[(long)w * CDIM])[lane] = o;
}

// ---------------- batch norm ----------------
__global__ void stats_kernel(const float* __restrict__ y) {
    int c = threadIdx.x;
    int r0 = blockIdx.x * 64;
    int rend = min(r0 + 64, NNODES);
    float s = 0.f, q = 0.f;
    for (int r = r0; r < rend; r++) {
        float v = y[r * CDIM + c];
        s += v;
        q = fmaf(v, v, q);
    }
    atomicAdd(&g_stats[c], s);
    atomicAdd(&g_stats[CDIM + c], q);
}

__global__ void bnfinal_kernel(const float* __restrict__ gamma,
                               const float* __restrict__ beta) {
    int c = threadIdx.x;
    float mean = g_stats[c] * (1.f / NNODES);
    float var  = g_stats[CDIM + c] * (1.f / NNODES) - mean * mean;
    float rstd = rsqrtf(var + 1e-5f);
    float sc = gamma[c] * rstd;
    g_ss[c] = sc;
    g_ss[CDIM + c] = beta[c] - mean * sc;
}

// norm + relu; optionally emit bf16 hi/lo for next layer (fused convA, K_next=128).
// Also zeroes g_s/g_d (score accumulators) and g_stats for the next layer.
__global__ void norm_kernel(float* __restrict__ y, int relu, int emit,
                            __nv_bfloat16* __restrict__ abf) {
    int i = blockIdx.x * blockDim.x + threadIdx.x;
    if (i >= NNODES * CDIM) return;
    if (i < NNODES * HMAX) { g_s[i] = 0.f; g_d[i] = 0.f; }
    if (i < 2 * CDIM) g_stats[i] = 0.f;
    int c = i & (CDIM - 1);
    float v = fmaf(y[i], g_ss[c], g_ss[CDIM + c]);
    if (relu) v = fmaxf(v, 0.f);
    y[i] = v;
    if (emit) {
        int r = i >> 7;
        __nv_bfloat16 hi = __float2bfloat16_rn(v);
        float rsd = v - __bfloat162float(hi);
        abf[(long)r * 256 + c] = hi;
        abf[(long)r * 256 + CDIM + c] = __float2bfloat16_rn(rsd);
    }
}

// ---------------- host ----------------
extern "C" void kernel_launch(void* const* d_in, const int* in_sizes, int n_in,
                              void* d_out, int out_size) {
    const float* x = (const float*)d_in[0];
    const int* ei_raw = (const int*)d_in[1];
    int E = in_sizes[1] / 2;
    int Etot = E + NNODES;

    float *hbuf, *buf1, *buf2;
    cudaGetSymbolAddress((void**)&hbuf, g_h);
    cudaGetSymbolAddress((void**)&buf1, g_buf1);
    cudaGetSymbolAddress((void**)&buf2, g_buf2);
    __nv_bfloat16 *abf, *bbf;
    cudaGetSymbolAddress((void**)&abf, g_abf);
    cudaGetSymbolAddress((void**)&bbf, g_bbf);

    detect_kernel<<<1, 128>>>(ei_raw);
    decode_kernel<<<(Etot + 255) / 256, 256>>>(ei_raw, E, Etot);

    csr_zero_kernel<<<(NNODES + 255) / 256, 256>>>();
    csr_count_kernel<<<(Etot + 255) / 256, 256>>>(Etot);
    csr_scan1_kernel<<<NSCANB, 256>>>();
    csr_scan2_kernel<<<1, 256>>>();
    csr_fix_kernel<<<(NNODES + 255) / 256, 256>>>();
    csr_place_kernel<<<(Etot + 255) / 256, 256>>>(Etot);

    const int Ks[3] = {256, 128, 128};
    const int Hs[3] = {4, 4, 1};
    float* outs[3] = {buf1, buf2, (float*)d_out};

    for (int L = 0; L < 3; L++) {
        const float* W     = (const float*)d_in[2 + 6 * L];
        const float* asrc  = (const float*)d_in[3 + 6 * L];
        const float* adst  = (const float*)d_in[4 + 6 * L];
        const float* bias  = (const float*)d_in[5 + 6 * L];
        const float* gamma = (const float*)d_in[6 + 6 * L];
        const float* beta  = (const float*)d_in[7 + 6 * L];
        int K = Ks[L], H = Hs[L], M = H * CDIM;
        float* y = outs[L];

        if (L == 0) {
            long atot = (long)NNODES * K;
            convA_kernel<<<(int)((atot + 255) / 256), 256>>>(x, abf, atot, K);
        }
        convB_kernel<<<(K * M + 255) / 256, 256>>>(W, bbf, K, M);

        dim3 gg(M / 128, (NNODES + 127) / 128);
        mma_gemm_kernel<<<gg, 256>>>(abf, bbf, hbuf, NNODES, K, M, asrc, adst, H);

        int ablocks = (NNODES * 32 + 255) / 256;
        if (H == 4) attn_kernel<4><<<ablocks, 256>>>(hbuf, y, bias);
        else        attn_kernel<1><<<ablocks, 256>>>(hbuf, y, bias);

        stats_kernel<<<(NNODES + 63) / 64, CDIM>>>(y);
        bnfinal_kernel<<<1, CDIM>>>(gamma, beta);
        norm_kernel<<<(NNODES * CDIM + 255) / 256, 256>>>(y, (L < 2) ? 1 : 0,
                                                          (L < 2) ? 1 : 0, abf);
    }
}